// round 11
// baseline (speedup 1.0000x reference)
#include <cuda_runtime.h>

// Depthwise causal conv1d, channel-last. x:(B,L,D) fp32; w:(K=4,1,D); b:(D,).
// y[b,l,d] = bias[d] + sum_k x[b,l+k-3,d]*w[k,d]
//
// FINAL: converged optimum (rounds 1-10). 1024 blocks x 256 threads,
// CHUNK=32 fully unrolled sliding register window, default cache policies,
// default launch bounds (64 regs -> ~8 in-flight LDG.128/thread).
// 268MB app-level at ~7.0 TB/s (~88% of HBM3e spec for a 1:1 r/w stream);
// DRAM demand ~228MB after L2 halo/write absorption. Residual DRAM idle is
// bus turnaround + refresh — not kernel-addressable (issue 15%, fma 11%,
// latency coverage 2x over-provisioned).
// Measured-and-rejected alternatives: CHUNK 8/64, balanced strips,
// grid-stride, __ldcs streaming, 5-blocks/SM reg cap, front-batched unrolls.

#define CHUNK 32

__global__ void __launch_bounds__(256) dwconv_kernel(
    const float4* __restrict__ x,
    const float4* __restrict__ w,
    const float4* __restrict__ bias,
    float4* __restrict__ y,
    int L, int D4)
{
    const int d4 = blockIdx.x * blockDim.x + threadIdx.x;   // channel group
    const int l0 = blockIdx.y * CHUNK;                      // start of l slice
    const int b  = blockIdx.z;

    // weights (K=4) and bias in registers
    const float4 w0 = w[0 * D4 + d4];
    const float4 w1 = w[1 * D4 + d4];
    const float4 w2 = w[2 * D4 + d4];
    const float4 w3 = w[3 * D4 + d4];
    const float4 bb = bias[d4];

    const long base = (long)b * L * D4 + d4;   // index of (b, l=0, d4)

    // history window x[l0-3], x[l0-2], x[l0-1] (zero before sequence start)
    float4 h0, h1, h2;
    const float4 z4 = make_float4(0.f, 0.f, 0.f, 0.f);
    h0 = (l0 - 3 >= 0) ? x[base + (long)(l0 - 3) * D4] : z4;
    h1 = (l0 - 2 >= 0) ? x[base + (long)(l0 - 2) * D4] : z4;
    h2 = (l0 - 1 >= 0) ? x[base + (long)(l0 - 1) * D4] : z4;

    #pragma unroll
    for (int i = 0; i < CHUNK; ++i) {
        const long idx = base + (long)(l0 + i) * D4;
        const float4 xc = x[idx];
        float4 o;
        o.x = fmaf(w3.x, xc.x, fmaf(w2.x, h2.x, fmaf(w1.x, h1.x, fmaf(w0.x, h0.x, bb.x))));
        o.y = fmaf(w3.y, xc.y, fmaf(w2.y, h2.y, fmaf(w1.y, h1.y, fmaf(w0.y, h0.y, bb.y))));
        o.z = fmaf(w3.z, xc.z, fmaf(w2.z, h2.z, fmaf(w1.z, h1.z, fmaf(w0.z, h0.z, bb.z))));
        o.w = fmaf(w3.w, xc.w, fmaf(w2.w, h2.w, fmaf(w1.w, h1.w, fmaf(w0.w, h0.w, bb.w))));
        y[idx] = o;
        h0 = h1; h1 = h2; h2 = xc;
    }
}

extern "C" void kernel_launch(void* const* d_in, const int* in_sizes, int n_in,
                              void* d_out, int out_size)
{
    const float* x  = (const float*)d_in[0];
    const float* w  = (const float*)d_in[1];
    const float* bi = (const float*)d_in[2];
    float* y = (float*)d_out;

    const int D  = in_sizes[2];            // 2048
    const int BL = in_sizes[0] / D;        // B*L
    int L = 4096;
    if (BL % L != 0) L = BL;               // fallback for unexpected shapes
    const int B  = BL / L;
    const int D4 = D / 4;

    const int THREADS = 256;
    dim3 grid(D4 / THREADS, (L + CHUNK - 1) / CHUNK, B);
    dwconv_kernel<<<grid, THREADS>>>(
        (const float4*)x, (const float4*)w, (const float4*)bi,
        (float4*)y, L, D4);
}

// round 12
// speedup vs baseline: 1.0007x; 1.0007x over previous
#include <cuda_runtime.h>

// Depthwise causal conv1d, channel-last. x:(B,L,D) fp32; w:(K=4,1,D); b:(D,).
// y[b,l,d] = bias[d] + sum_k x[b,l+k-3,d]*w[k,d]
//
// FINAL: converged optimum (rounds 1-11; 5x reproduced at 47.6us).
// 1024 blocks x 256 threads, CHUNK=32 fully unrolled sliding register
// window, default cache policies, default launch bounds (64 regs ->
// ~8 in-flight LDG.128/thread). 268MB app-level at ~7.0 TB/s (~88% of
// HBM3e spec for a 1:1 r/w stream); DRAM demand ~228MB after L2 halo/write
// absorption. Residual DRAM idle = bus turnaround + refresh (not
// kernel-addressable: issue 15%, fma 11%, latency coverage 2x).
// Measured-and-rejected: CHUNK 8/64, balanced strips, grid-stride,
// __ldcs streaming, 5-blocks/SM reg cap, front-batched x4/x8 unrolls.

#define CHUNK 32

__global__ void __launch_bounds__(256) dwconv_kernel(
    const float4* __restrict__ x,
    const float4* __restrict__ w,
    const float4* __restrict__ bias,
    float4* __restrict__ y,
    int L, int D4)
{
    const int d4 = blockIdx.x * blockDim.x + threadIdx.x;   // channel group
    const int l0 = blockIdx.y * CHUNK;                      // start of l slice
    const int b  = blockIdx.z;

    // weights (K=4) and bias in registers
    const float4 w0 = w[0 * D4 + d4];
    const float4 w1 = w[1 * D4 + d4];
    const float4 w2 = w[2 * D4 + d4];
    const float4 w3 = w[3 * D4 + d4];
    const float4 bb = bias[d4];

    const long base = (long)b * L * D4 + d4;   // index of (b, l=0, d4)

    // history window x[l0-3], x[l0-2], x[l0-1] (zero before sequence start)
    float4 h0, h1, h2;
    const float4 z4 = make_float4(0.f, 0.f, 0.f, 0.f);
    h0 = (l0 - 3 >= 0) ? x[base + (long)(l0 - 3) * D4] : z4;
    h1 = (l0 - 2 >= 0) ? x[base + (long)(l0 - 2) * D4] : z4;
    h2 = (l0 - 1 >= 0) ? x[base + (long)(l0 - 1) * D4] : z4;

    #pragma unroll
    for (int i = 0; i < CHUNK; ++i) {
        const long idx = base + (long)(l0 + i) * D4;
        const float4 xc = x[idx];
        float4 o;
        o.x = fmaf(w3.x, xc.x, fmaf(w2.x, h2.x, fmaf(w1.x, h1.x, fmaf(w0.x, h0.x, bb.x))));
        o.y = fmaf(w3.y, xc.y, fmaf(w2.y, h2.y, fmaf(w1.y, h1.y, fmaf(w0.y, h0.y, bb.y))));
        o.z = fmaf(w3.z, xc.z, fmaf(w2.z, h2.z, fmaf(w1.z, h1.z, fmaf(w0.z, h0.z, bb.z))));
        o.w = fmaf(w3.w, xc.w, fmaf(w2.w, h2.w, fmaf(w1.w, h1.w, fmaf(w0.w, h0.w, bb.w))));
        y[idx] = o;
        h0 = h1; h1 = h2; h2 = xc;
    }
}

extern "C" void kernel_launch(void* const* d_in, const int* in_sizes, int n_in,
                              void* d_out, int out_size)
{
    const float* x  = (const float*)d_in[0];
    const float* w  = (const float*)d_in[1];
    const float* bi = (const float*)d_in[2];
    float* y = (float*)d_out;

    const int D  = in_sizes[2];            // 2048
    const int BL = in_sizes[0] / D;        // B*L
    int L = 4096;
    if (BL % L != 0) L = BL;               // fallback for unexpected shapes
    const int B  = BL / L;
    const int D4 = D / 4;

    const int THREADS = 256;
    dim3 grid(D4 / THREADS, (L + CHUNK - 1) / CHUNK, B);
    dwconv_kernel<<<grid, THREADS>>>(
        (const float4*)x, (const float4*)w, (const float4*)bi,
        (float4*)y, L, D4);
}